// round 1
// baseline (speedup 1.0000x reference)
#include <cuda_runtime.h>
#include <math.h>

// ---------------------------------------------------------------------------
// Problem constants (fixed by the reference): B=256, L=8192, K=5, C=64, CO=4
// ---------------------------------------------------------------------------
#define LLEN     8192
#define TILE     121          // output points per CTA tile
#define NTILES   68           // ceil(8192/121); tail wraps periodically (duplicate, identical writes)
#define Y_N      136          // y / Prim halo rows: j in [-8, TILE+6]
#define H1_N     132          // h1 rows: j in [-6, TILE+4]
#define H2_N     128          // h2 rows: j in [-4, TILE+2]  (exactly 2^7 -> zero wave waste)
#define G_N      124          // grad rows: j in [-2, TILE]
#define PHI_N    123          // phi rows: p in [-1, TILE]
#define NTHREADS 512

// Shared-memory layout (float offsets)
#define SW2_OFF  0                         // 5*64*64  = 20480
#define SH1_OFF  (SW2_OFF + 5*64*64)       // 64*H1_N  = 8448   (transposed: [ci][row])
#define SH2_OFF  (SH1_OFF + 64*H1_N)       // H2_N*65  = 8320   (row stride 65: conflict-free conv3 reads)
#define SW1_OFF  (SH2_OFF + H2_N*65)       // 320
#define SW3_OFF  (SW1_OFF + 5*64)          // 1280
#define SB1_OFF  (SW3_OFF + 5*64*4)        // 64
#define SB2_OFF  (SB1_OFF + 64)            // 64
#define SY_OFF   (SB2_OFF + 64)            // Y_N
#define SP_OFF   (SY_OFF + Y_N)            // Y_N
#define SG_OFF   (SP_OFF + Y_N)            // G_N
#define SPHI_OFF (SG_OFF + G_N)            // PHI_N
#define SMEM_FLOATS (SPHI_OFF + PHI_N)
#define SMEM_BYTES  (SMEM_FLOATS * 4)

// Static polynomial-accuracy constants (derivative=1, constraint_order=1, K=5)
// ALPHA_P solves the Vandermonde system: classic 4th-order central difference.
#define AP0  0.0833333333333333f   //  1/12
#define AP1 -0.6666666666666667f   // -2/3
#define AP3  0.6666666666666667f   //  2/3
#define AP4 -0.0833333333333333f   // -1/12
// NULL_BASIS = rows 1..4 of the Householder reflector H = I - tau v v^T that
// LAPACK dgesdd produces for svd([[1,1,1,1,1]]):
//   NB[c][0] = -1/sqrt(5);  NB[c][k>=1] = (k==c+1 ? 1 : 0) - 1/(5+sqrt(5))
// => patch . NB[c] = (-1/sqrt5)*p0 - 0.1381966*(p1+p2+p3+p4) + p[c+1]
#define NB_P0 -0.4472135954999579f
#define NB_S4 -0.1381966011250105f

#define DXH 0.0078125f   // 0.5 * DX, DX = 1/64
#define CFL 0.01f

__device__ float g_mn[4096];
__device__ float g_inv[4096];

// ---------------------------------------------------------------------------
// Pass 1: per-row min/max -> g_mn[b], g_inv[b] = 1/max((mx-mn)/2, 1e-4)
// ---------------------------------------------------------------------------
__global__ void rowminmax_kernel(const float* __restrict__ Prim) {
    __shared__ float smx[8], smn[8];
    int b = blockIdx.x;
    const float4* P = reinterpret_cast<const float4*>(Prim + (size_t)b * LLEN);
    float mx = -3.402823466e38f, mn = 3.402823466e38f;
    for (int i = threadIdx.x; i < LLEN / 4; i += blockDim.x) {
        float4 v = P[i];
        mx = fmaxf(mx, fmaxf(fmaxf(v.x, v.y), fmaxf(v.z, v.w)));
        mn = fminf(mn, fminf(fminf(v.x, v.y), fminf(v.z, v.w)));
    }
    #pragma unroll
    for (int o = 16; o > 0; o >>= 1) {
        mx = fmaxf(mx, __shfl_xor_sync(0xffffffffu, mx, o));
        mn = fminf(mn, __shfl_xor_sync(0xffffffffu, mn, o));
    }
    int w = threadIdx.x >> 5;
    if ((threadIdx.x & 31) == 0) { smx[w] = mx; smn[w] = mn; }
    __syncthreads();
    if (threadIdx.x == 0) {
        #pragma unroll
        for (int i = 1; i < 8; i++) { mx = fmaxf(mx, smx[i]); mn = fminf(mn, smn[i]); }
        float scale = (mx - mn) * 0.5f;
        g_mn[b]  = mn;
        g_inv[b] = 1.0f / fmaxf(scale, 1e-4f);
    }
}

// ---------------------------------------------------------------------------
// Pass 2: fully fused conv stack + stencil + TVD flux for one (batch, tile)
// ---------------------------------------------------------------------------
__global__ void __launch_bounds__(NTHREADS, 1)
fused_kernel(const float* __restrict__ Prim,
             const float* __restrict__ W1, const float* __restrict__ b1,
             const float* __restrict__ W2, const float* __restrict__ b2,
             const float* __restrict__ W3, const float* __restrict__ b3,
             float* __restrict__ Out) {
    extern __shared__ float sm[];
    float* sW2  = sm + SW2_OFF;
    float* sh1  = sm + SH1_OFF;   // [ci][row], row stride H1_N (multiple of 4 -> aligned float4 rows)
    float* sh2  = sm + SH2_OFF;   // [row][co], row stride 65
    float* sW1  = sm + SW1_OFF;
    float* sW3  = sm + SW3_OFF;
    float* sb1  = sm + SB1_OFF;
    float* sb2  = sm + SB2_OFF;
    float* sy   = sm + SY_OFF;
    float* sP   = sm + SP_OFF;
    float* sg   = sm + SG_OFF;
    float* sphi = sm + SPHI_OFF;

    const int tid = threadIdx.x;
    const int b   = blockIdx.y;
    const int s   = blockIdx.x * TILE;           // tile start (global l of local j=0)
    const float* P = Prim + (size_t)b * LLEN;

    // ---- stage weights + input halo ----
    for (int i = tid; i < 5 * 64 * 64; i += NTHREADS) sW2[i] = W2[i];
    for (int i = tid; i < 5 * 64;      i += NTHREADS) sW1[i] = W1[i];
    for (int i = tid; i < 5 * 64 * 4;  i += NTHREADS) sW3[i] = W3[i];
    if (tid < 64) { sb1[tid] = b1[tid]; sb2[tid] = b2[tid]; }
    const float mnb = g_mn[b], invb = g_inv[b];
    for (int i = tid; i < Y_N; i += NTHREADS) {
        int gidx = (s + i - 8 + LLEN) & (LLEN - 1);
        float p = P[gidx];
        sP[i] = p;
        sy[i] = (p - mnb) * invb - 1.0f;
    }
    __syncthreads();

    // ---- conv1: scalar y -> h1[132][64], stored transposed sh1[c][row] ----
    {
        int c  = tid & 63;
        int lg = tid >> 6;                        // 0..7
        float w0 = sW1[c], w1 = sW1[64 + c], w2 = sW1[128 + c],
              w3 = sW1[192 + c], w4 = sW1[256 + c];
        float bb = sb1[c];
        for (int r = lg; r < H1_N; r += 8) {
            float acc = bb;
            acc = fmaf(w0, sy[r],     acc);
            acc = fmaf(w1, sy[r + 1], acc);
            acc = fmaf(w2, sy[r + 2], acc);
            acc = fmaf(w3, sy[r + 3], acc);
            acc = fmaf(w4, sy[r + 4], acc);
            sh1[c * H1_N + r] = tanhf(acc);
        }
    }
    __syncthreads();

    // ---- conv2: h1 -> h2[128][64]  (the dominant GEMM-like loop) ----
    {
        int cg = tid & 15;                        // co block: co = 4*cg
        int lg = tid >> 4;                        // 0..31
        int r0 = lg * 4;                          // h2 rows r0..r0+3 (needs h1 rows r0..r0+7)
        float acc[4][4];
        #pragma unroll
        for (int j = 0; j < 4; j++)
            #pragma unroll
            for (int c = 0; c < 4; c++) acc[j][c] = 0.0f;

        const int wbase = 4 * cg;
        for (int ci = 0; ci < 64; ci++) {
            const float* h1row = &sh1[ci * H1_N + r0];
            float4 a = *reinterpret_cast<const float4*>(h1row);
            float4 q = *reinterpret_cast<const float4*>(h1row + 4);
            float h[8] = {a.x, a.y, a.z, a.w, q.x, q.y, q.z, q.w};
            #pragma unroll
            for (int k = 0; k < 5; k++) {
                float4 wv = *reinterpret_cast<const float4*>(&sW2[(k * 64 + ci) * 64 + wbase]);
                #pragma unroll
                for (int j = 0; j < 4; j++) {
                    float hv = h[k + j];
                    acc[j][0] = fmaf(hv, wv.x, acc[j][0]);
                    acc[j][1] = fmaf(hv, wv.y, acc[j][1]);
                    acc[j][2] = fmaf(hv, wv.z, acc[j][2]);
                    acc[j][3] = fmaf(hv, wv.w, acc[j][3]);
                }
            }
        }
        #pragma unroll
        for (int j = 0; j < 4; j++)
            #pragma unroll
            for (int c = 0; c < 4; c++)
                sh2[(r0 + j) * 65 + wbase + c] = tanhf(acc[j][c] + sb2[wbase + c]);
    }
    __syncthreads();

    // ---- conv3 + null-space correction + stencil derivative: grad[124] ----
    if (tid < G_N) {
        int ic = tid;
        float c0 = b3[0], c1 = b3[1], c2 = b3[2], c3 = b3[3];
        #pragma unroll
        for (int k = 0; k < 5; k++) {
            const float* h2row = &sh2[(ic + k) * 65];
            const float4* wrow = reinterpret_cast<const float4*>(&sW3[k * 64 * 4]);
            #pragma unroll 8
            for (int ci = 0; ci < 64; ci++) {
                float hv = h2row[ci];
                float4 wv = wrow[ci];
                c0 = fmaf(hv, wv.x, c0);
                c1 = fmaf(hv, wv.y, c1);
                c2 = fmaf(hv, wv.z, c2);
                c3 = fmaf(hv, wv.w, c3);
            }
        }
        // patches: Prim[j + k - 2], j = ic - 2  -> sP[ic+4 .. ic+8]
        float p0 = sP[ic + 4], p1 = sP[ic + 5], p2 = sP[ic + 6],
              p3 = sP[ic + 7], p4 = sP[ic + 8];
        float dotp = AP0 * p0 + AP1 * p1 + AP3 * p3 + AP4 * p4;
        float S4   = p1 + p2 + p3 + p4;
        float base = NB_P0 * p0 + NB_S4 * S4;
        float corr = c0 * (base + p1) + c1 * (base + p2)
                   + c2 * (base + p3) + c3 * (base + p4);
        sg[ic] = (dotp + corr) * 64.0f;          // / DX
    }
    __syncthreads();

    // ---- TVD limiter phi at p in [-1, TILE]  (grad[p] = sg[p+2]) ----
    if (tid < PHI_N) {
        float gcur = sg[tid + 1];                // grad[p]
        float gpre = sg[tid];                    // grad[p-1]
        float aa = (gcur < 0.0f) ? -1.0f : 1.0f; // min(sign,0)*2+1
        float ri = gpre / (fmaxf(fabsf(gcur), 1e-15f) * aa);
        sphi[tid] = (ri * ri + ri) / (ri * ri + 1.0f);
    }
    __syncthreads();

    // ---- Godunov flux + update.  flux(f): Prim=sP[f+8], phi=sphi[f+1], grad=sg[f+2]
    if (tid < TILE) {
        int j = tid;
        float fl[2];
        #pragma unroll
        for (int t = 0; t < 2; t++) {
            int f = j - 1 + t;
            float uL = fmaf(DXH * sphi[f + 1], sg[f + 2], sP[f + 8]);
            float uR = fmaf(-DXH * sphi[f + 2], sg[f + 3], sP[f + 9]);
            fl[t] = 0.25f * (uL * uL + uR * uR)
                  - 0.25f * fabsf(uL + uR) * (uR - uL);
        }
        int gidx = (s + j) & (LLEN - 1);
        Out[(size_t)b * LLEN + gidx] = sP[j + 8] - CFL * (fl[1] - fl[0]);
    }
}

// ---------------------------------------------------------------------------
// Launch
// ---------------------------------------------------------------------------
extern "C" void kernel_launch(void* const* d_in, const int* in_sizes, int n_in,
                              void* d_out, int out_size) {
    const float* Prim = (const float*)d_in[0];
    const float* W1   = (const float*)d_in[1];
    const float* b1   = (const float*)d_in[2];
    const float* W2   = (const float*)d_in[3];
    const float* b2   = (const float*)d_in[4];
    const float* W3   = (const float*)d_in[5];
    const float* b3   = (const float*)d_in[6];
    float* Out = (float*)d_out;

    int B = in_sizes[0] / LLEN;

    static int attr_set = -1;
    // (idempotent, deterministic; not a stream op so safe under graph capture)
    cudaFuncSetAttribute(fused_kernel,
                         cudaFuncAttributeMaxDynamicSharedMemorySize, SMEM_BYTES);
    (void)attr_set;

    rowminmax_kernel<<<B, 256>>>(Prim);
    fused_kernel<<<dim3(NTILES, B), NTHREADS, SMEM_BYTES>>>(
        Prim, W1, b1, W2, b2, W3, b3, Out);
}

// round 3
// speedup vs baseline: 4.8624x; 4.8624x over previous
#include <cuda_runtime.h>
#include <cuda_bf16.h>
#include <math.h>
#include <stdint.h>

// ---------------------------------------------------------------------------
// Problem constants: B=256, L=8192, K=5, C=64, CO=4
// ---------------------------------------------------------------------------
#define LLEN     8192
#define TILE     121
#define NTILES   68          // ceil(8192/121); tail wraps (duplicate identical writes)
#define Y_N      136         // y/Prim halo rows
#define H1_ROWS  132
#define H2_ROWS  132         // 128 computed + 4 garbage tail (read by last mma3 stripe)
#define G_N      124
#define PHI_N    123
#define NTHREADS 512

// bf16 row stride for h1/h2/W2: 72 elems = 144 B (9*16B -> conflict-free ldmatrix)
#define RS       72
#define RSB      144

// smem byte layout
#define H1_OFF   0
#define H2_OFF   (H1_OFF + H2_ROWS * RSB)          // 19008
#define W2_OFF   (H2_OFF + H2_ROWS * RSB)          // 38016 ; 5*64*144 = 46080
#define W3_OFF   (W2_OFF + 5 * 64 * RSB)           // 84096 ; 5*64*16  = 5120
#define D3_OFF   (W3_OFF + 5 * 64 * 16)            // 89216 ; 128*8*4  = 4096
#define MISC_OFF (D3_OFF + 4096)                   // 93312
#define SMEM_DYN (MISC_OFF + 4096)

// polynomial-accuracy constants (K=5, derivative=1, constraint_order=1)
#define AP0  0.0833333333333333f
#define AP1 -0.6666666666666667f
#define AP3  0.6666666666666667f
#define AP4 -0.0833333333333333f
#define NB_P0 -0.4472135954999579f
#define NB_S4 -0.1381966011250105f
#define DXH 0.0078125f
#define CFL 0.01f

__device__ float g_mn[4096];
__device__ float g_inv[4096];
__device__ __align__(16) unsigned char g_W2p[5 * 64 * RSB];  // bf16 [tap][ci][co(pad 72)]
__device__ __align__(16) unsigned char g_W3p[5 * 64 * 16];   // bf16 [tap][ci][co(pad 8)]

// ---------------------------------------------------------------------------
// helpers
// ---------------------------------------------------------------------------
__device__ __forceinline__ uint32_t smem_u32(const void* p) {
    uint32_t a;
    asm("{ .reg .u64 t; cvta.to.shared.u64 t, %1; cvt.u32.u64 %0, t; }" : "=r"(a) : "l"(p));
    return a;
}
__device__ __forceinline__ float tanha(float x) {
    float y; asm("tanh.approx.f32 %0, %1;" : "=f"(y) : "f"(x)); return y;
}
#define CVTBF2(res, lo, hi) \
    asm("cvt.rn.bf16x2.f32 %0, %1, %2;" : "=r"(res) : "f"(hi), "f"(lo))
#define STS128(a, r0, r1, r2, r3) \
    asm volatile("st.shared.v4.b32 [%0], {%1, %2, %3, %4};" :: "r"(a), "r"(r0), "r"(r1), "r"(r2), "r"(r3) : "memory")

__device__ __forceinline__ void ldsm_x4(uint32_t& r0, uint32_t& r1, uint32_t& r2,
                                        uint32_t& r3, uint32_t a) {
    asm volatile("ldmatrix.sync.aligned.m8n8.x4.shared.b16 {%0,%1,%2,%3}, [%4];"
                 : "=r"(r0), "=r"(r1), "=r"(r2), "=r"(r3) : "r"(a));
}
__device__ __forceinline__ void ldsm_x4t(uint32_t& r0, uint32_t& r1, uint32_t& r2,
                                         uint32_t& r3, uint32_t a) {
    asm volatile("ldmatrix.sync.aligned.m8n8.x4.trans.shared.b16 {%0,%1,%2,%3}, [%4];"
                 : "=r"(r0), "=r"(r1), "=r"(r2), "=r"(r3) : "r"(a));
}
__device__ __forceinline__ void ldsm_x2t(uint32_t& r0, uint32_t& r1, uint32_t a) {
    asm volatile("ldmatrix.sync.aligned.m8n8.x2.trans.shared.b16 {%0,%1}, [%2];"
                 : "=r"(r0), "=r"(r1) : "r"(a));
}
__device__ __forceinline__ void mma16816(float& c0, float& c1, float& c2, float& c3,
                                         uint32_t a0, uint32_t a1, uint32_t a2, uint32_t a3,
                                         uint32_t b0, uint32_t b1) {
    asm volatile("mma.sync.aligned.m16n8k16.row.col.f32.bf16.bf16.f32 "
                 "{%0,%1,%2,%3}, {%4,%5,%6,%7}, {%8,%9}, {%0,%1,%2,%3};"
                 : "+f"(c0), "+f"(c1), "+f"(c2), "+f"(c3)
                 : "r"(a0), "r"(a1), "r"(a2), "r"(a3), "r"(b0), "r"(b1));
}

// ---------------------------------------------------------------------------
// Pre-pass 1: per-row min/max
// ---------------------------------------------------------------------------
__global__ void rowminmax_kernel(const float* __restrict__ Prim) {
    __shared__ float smx[8], smn[8];
    int b = blockIdx.x;
    const float4* P = reinterpret_cast<const float4*>(Prim + (size_t)b * LLEN);
    float mx = -3.402823466e38f, mn = 3.402823466e38f;
    for (int i = threadIdx.x; i < LLEN / 4; i += blockDim.x) {
        float4 v = P[i];
        mx = fmaxf(mx, fmaxf(fmaxf(v.x, v.y), fmaxf(v.z, v.w)));
        mn = fminf(mn, fminf(fminf(v.x, v.y), fminf(v.z, v.w)));
    }
    #pragma unroll
    for (int o = 16; o > 0; o >>= 1) {
        mx = fmaxf(mx, __shfl_xor_sync(0xffffffffu, mx, o));
        mn = fminf(mn, __shfl_xor_sync(0xffffffffu, mn, o));
    }
    int w = threadIdx.x >> 5;
    if ((threadIdx.x & 31) == 0) { smx[w] = mx; smn[w] = mn; }
    __syncthreads();
    if (threadIdx.x == 0) {
        #pragma unroll
        for (int i = 1; i < 8; i++) { mx = fmaxf(mx, smx[i]); mn = fminf(mn, smn[i]); }
        g_mn[b]  = mn;
        g_inv[b] = 1.0f / fmaxf((mx - mn) * 0.5f, 1e-4f);
    }
}

// ---------------------------------------------------------------------------
// Pre-pass 2: convert W2/W3 to bf16, transposed-to-[tap][ci][co] padded layout
// W2 input layout [K][Cin][Cout] already [tap][ci][co]; just bf16 + pad stride.
// ---------------------------------------------------------------------------
__global__ void wconvert_kernel(const float* __restrict__ W2,
                                const float* __restrict__ W3) {
    int idx = blockIdx.x * blockDim.x + threadIdx.x;
    if (idx < 5 * 64 * 64) {
        int k = idx >> 12, ci = (idx >> 6) & 63, co = idx & 63;
        *reinterpret_cast<__nv_bfloat16*>(
            g_W2p + (k * 64 + ci) * RSB + co * 2) = __float2bfloat16(W2[idx]);
    }
    if (idx < 5 * 64 * 8) {
        int k = idx >> 9, ci = (idx >> 3) & 63, co = idx & 7;
        float f = (co < 4) ? W3[(k * 64 + ci) * 4 + co] : 0.0f;
        *reinterpret_cast<__nv_bfloat16*>(
            g_W3p + (k * 64 + ci) * 16 + co * 2) = __float2bfloat16(f);
    }
}

// ---------------------------------------------------------------------------
// Fused kernel
// ---------------------------------------------------------------------------
__global__ void __launch_bounds__(NTHREADS, 2)
fused_kernel(const float* __restrict__ Prim,
             const float* __restrict__ W1, const float* __restrict__ b1,
             const float* __restrict__ b2, const float* __restrict__ b3,
             float* __restrict__ Out) {
    extern __shared__ char smc[];
    const uint32_t smb = smem_u32(smc);

    float* sD3  = (float*)(smc + D3_OFF);       // [128][8]
    float* sy   = (float*)(smc + MISC_OFF);     // 136
    float* sP   = sy + 136;                     // 136
    float* sg   = sP + 136;                     // 128
    float* sphi = sg + 128;                     // 128
    float* sW1  = sphi + 128;                   // 320
    float* sb1  = sW1 + 320;                    // 64
    float* sb2  = sb1 + 64;                     // 64

    const int tid  = threadIdx.x;
    const int wid  = tid >> 5;
    const int lane = tid & 31;
    const int b    = blockIdx.y;
    const int s    = blockIdx.x * TILE;
    const float* P = Prim + (size_t)b * LLEN;

    // ---- stage weights + input halo ----
    {
        const int4* s2 = (const int4*)g_W2p;
        int4* d2 = (int4*)(smc + W2_OFF);
        for (int i = tid; i < 5 * 64 * RSB / 16; i += NTHREADS) d2[i] = s2[i];
        const int4* s3 = (const int4*)g_W3p;
        int4* d3 = (int4*)(smc + W3_OFF);
        for (int i = tid; i < 5 * 64; i += NTHREADS) d3[i] = s3[i];
    }
    if (tid < 320) sW1[tid] = W1[tid];
    if (tid < 64) { sb1[tid] = b1[tid]; sb2[tid] = b2[tid]; }
    const float mnb = g_mn[b], invb = g_inv[b];
    for (int i = tid; i < Y_N; i += NTHREADS) {
        int gidx = (s + i - 8 + LLEN) & (LLEN - 1);
        float p = P[gidx];
        sP[i] = p;
        sy[i] = (p - mnb) * invb - 1.0f;
    }
    __syncthreads();

    // ---- conv1: y -> h1 bf16 [132][64] stride RS ----
    {
        int chunk = tid & 7;         // ci chunk of 8
        int rs    = tid >> 3;        // row slot 0..63
        int c0    = chunk * 8;
        float wt[5][8], bb[8];
        #pragma unroll
        for (int t = 0; t < 5; t++)
            #pragma unroll
            for (int j = 0; j < 8; j++) wt[t][j] = sW1[t * 64 + c0 + j];
        #pragma unroll
        for (int j = 0; j < 8; j++) bb[j] = sb1[c0 + j];

        for (int m = rs; m < H1_ROWS; m += 64) {
            float y0 = sy[m], y1 = sy[m+1], y2 = sy[m+2], y3 = sy[m+3], y4 = sy[m+4];
            float h[8];
            #pragma unroll
            for (int j = 0; j < 8; j++) {
                float acc = bb[j];
                acc = fmaf(wt[0][j], y0, acc);
                acc = fmaf(wt[1][j], y1, acc);
                acc = fmaf(wt[2][j], y2, acc);
                acc = fmaf(wt[3][j], y3, acc);
                acc = fmaf(wt[4][j], y4, acc);
                h[j] = tanha(acc);
            }
            uint32_t pk[4];
            #pragma unroll
            for (int i = 0; i < 4; i++) CVTBF2(pk[i], h[2*i], h[2*i+1]);
            STS128(smb + H1_OFF + m * RSB + chunk * 16, pk[0], pk[1], pk[2], pk[3]);
        }
    }
    __syncthreads();

    // ---- conv2 via mma.sync: D2[128][64] += A(h1 shifted) * B(W2) ----
    {
        int wr = wid & 7, wc = wid >> 3;
        int r0 = wr * 16;
        int n0 = wc * 32;
        float acc[4][4];
        #pragma unroll
        for (int t = 0; t < 4; t++)
            #pragma unroll
            for (int j = 0; j < 4; j++) acc[t][j] = 0.0f;

        int arow_l = (lane & 15);
        int acol_l = (lane >> 4) * 8;

        #pragma unroll
        for (int tap = 0; tap < 5; tap++) {
            #pragma unroll
            for (int cc = 0; cc < 4; cc++) {
                uint32_t a0, a1, a2, a3;
                ldsm_x4(a0, a1, a2, a3,
                        smb + H1_OFF + (r0 + tap + arow_l) * RSB
                            + (cc * 16 + acol_l) * 2);
                uint32_t b0a, b1a, b0b, b1b;
                uint32_t wb = smb + W2_OFF + (tap * 64 + cc * 16 + arow_l) * RSB;
                ldsm_x4t(b0a, b1a, b0b, b1b, wb + (n0 + acol_l) * 2);
                uint32_t c0a, c1a, c0b, c1b;
                ldsm_x4t(c0a, c1a, c0b, c1b, wb + (n0 + 16 + acol_l) * 2);
                mma16816(acc[0][0], acc[0][1], acc[0][2], acc[0][3], a0, a1, a2, a3, b0a, b1a);
                mma16816(acc[1][0], acc[1][1], acc[1][2], acc[1][3], a0, a1, a2, a3, b0b, b1b);
                mma16816(acc[2][0], acc[2][1], acc[2][2], acc[2][3], a0, a1, a2, a3, c0a, c1a);
                mma16816(acc[3][0], acc[3][1], acc[3][2], acc[3][3], a0, a1, a2, a3, c0b, c1b);
            }
        }
        __syncthreads();   // h1 reads done before h2 writes start? (different buffers; sync for W-after-R not needed, but cheap safety for D3/h2 ordering below)

        // epilogue: bias + tanh -> h2 bf16
        int rA = r0 + (lane >> 2);
        int colb = (lane & 3) * 2;
        #pragma unroll
        for (int t = 0; t < 4; t++) {
            int col = n0 + t * 8 + colb;
            float bL = sb2[col], bH = sb2[col + 1];
            uint32_t p0, p1;
            CVTBF2(p0, tanha(acc[t][0] + bL), tanha(acc[t][1] + bH));
            CVTBF2(p1, tanha(acc[t][2] + bL), tanha(acc[t][3] + bH));
            *(uint32_t*)(smc + H2_OFF + rA * RSB + col * 2) = p0;
            *(uint32_t*)(smc + H2_OFF + (rA + 8) * RSB + col * 2) = p1;
        }
    }
    __syncthreads();

    // ---- conv3 via mma.sync: D3[128][8] ----
    if (wid < 8) {
        int r0 = wid * 16;
        float acc[4] = {0.f, 0.f, 0.f, 0.f};
        int arow_l = (lane & 15);
        int acol_l = (lane >> 4) * 8;
        #pragma unroll
        for (int tap = 0; tap < 5; tap++) {
            #pragma unroll
            for (int cc = 0; cc < 4; cc++) {
                uint32_t a0, a1, a2, a3;
                ldsm_x4(a0, a1, a2, a3,
                        smb + H2_OFF + (r0 + tap + arow_l) * RSB
                            + (cc * 16 + acol_l) * 2);
                uint32_t b0, b1;
                ldsm_x2t(b0, b1, smb + W3_OFF + (tap * 64 + cc * 16 + arow_l) * 16);
                mma16816(acc[0], acc[1], acc[2], acc[3], a0, a1, a2, a3, b0, b1);
            }
        }
        int rA = r0 + (lane >> 2);
        int colb = (lane & 3) * 2;
        *(float2*)&sD3[rA * 8 + colb]       = make_float2(acc[0], acc[1]);
        *(float2*)&sD3[(rA + 8) * 8 + colb] = make_float2(acc[2], acc[3]);
    }
    __syncthreads();

    // ---- grad: null-space correction + stencil derivative ----
    if (tid < G_N) {
        int ic = tid;
        float c0 = sD3[ic * 8 + 0] + __ldg(&b3[0]);
        float c1 = sD3[ic * 8 + 1] + __ldg(&b3[1]);
        float c2 = sD3[ic * 8 + 2] + __ldg(&b3[2]);
        float c3 = sD3[ic * 8 + 3] + __ldg(&b3[3]);
        float p0 = sP[ic + 4], p1 = sP[ic + 5], p2 = sP[ic + 6],
              p3 = sP[ic + 7], p4 = sP[ic + 8];
        float dotp = AP0 * p0 + AP1 * p1 + AP3 * p3 + AP4 * p4;
        float S4   = p1 + p2 + p3 + p4;
        float base = NB_P0 * p0 + NB_S4 * S4;
        float corr = c0 * (base + p1) + c1 * (base + p2)
                   + c2 * (base + p3) + c3 * (base + p4);
        sg[ic] = (dotp + corr) * 64.0f;
    }
    __syncthreads();

    // ---- TVD limiter ----
    if (tid < PHI_N) {
        float gcur = sg[tid + 1];
        float gpre = sg[tid];
        float aa = (gcur < 0.0f) ? -1.0f : 1.0f;
        float ri = gpre / (fmaxf(fabsf(gcur), 1e-15f) * aa);
        sphi[tid] = (ri * ri + ri) / (ri * ri + 1.0f);
    }
    __syncthreads();

    // ---- Godunov flux + update ----
    if (tid < TILE) {
        int j = tid;
        float fl[2];
        #pragma unroll
        for (int t = 0; t < 2; t++) {
            int f = j - 1 + t;
            float uL = fmaf(DXH * sphi[f + 1], sg[f + 2], sP[f + 8]);
            float uR = fmaf(-DXH * sphi[f + 2], sg[f + 3], sP[f + 9]);
            fl[t] = 0.25f * (uL * uL + uR * uR)
                  - 0.25f * fabsf(uL + uR) * (uR - uL);
        }
        int gidx = (s + j) & (LLEN - 1);
        Out[(size_t)b * LLEN + gidx] = sP[j + 8] - CFL * (fl[1] - fl[0]);
    }
}

// ---------------------------------------------------------------------------
// Launch
// ---------------------------------------------------------------------------
extern "C" void kernel_launch(void* const* d_in, const int* in_sizes, int n_in,
                              void* d_out, int out_size) {
    const float* Prim = (const float*)d_in[0];
    const float* W1   = (const float*)d_in[1];
    const float* b1   = (const float*)d_in[2];
    const float* W2   = (const float*)d_in[3];
    const float* b2   = (const float*)d_in[4];
    const float* W3   = (const float*)d_in[5];
    const float* b3   = (const float*)d_in[6];
    float* Out = (float*)d_out;

    int B = in_sizes[0] / LLEN;

    cudaFuncSetAttribute(fused_kernel,
                         cudaFuncAttributeMaxDynamicSharedMemorySize, SMEM_DYN);

    rowminmax_kernel<<<B, 256>>>(Prim);
    wconvert_kernel<<<40, 512>>>(W2, W3);
    fused_kernel<<<dim3(NTILES, B), NTHREADS, SMEM_DYN>>>(
        Prim, W1, b1, b2, b3, Out);
}

// round 5
// speedup vs baseline: 4.8945x; 1.0066x over previous
#include <cuda_runtime.h>
#include <cuda_bf16.h>
#include <math.h>
#include <stdint.h>

// ---------------------------------------------------------------------------
// Problem constants: B=256, L=8192, K=5, C=64, CO=4
// ---------------------------------------------------------------------------
#define LLEN     8192
#define TILE     249         // output points per tile
#define NTILES   33          // ceil(8192/249); tail wraps (duplicate identical writes)
#define MTOT     256         // MMA M rows per tile
#define Y_N      264         // Prim/y halo rows: j in [-8, TILE+6]
#define H1_ROWS  260
#define H2_ROWS  260         // 256 computed + 4 garbage tail (read by last mma3 stripe)
#define G_N      252
#define PHI_N    251
#define NTHREADS 512
#define GRID_SM  148         // B200 sm_100a SM count (hardcoded; no runtime query)

// bf16 row stride for h1/h2/W2: 72 elems = 144 B (9*16B -> conflict-free ldmatrix)
#define RS       72
#define RSB      144

// smem byte layout
#define H1_OFF   0
#define H2_OFF   (H1_OFF + H1_ROWS * RSB)          // 37440
#define W2_OFF   (H2_OFF + H2_ROWS * RSB)          // 74880 ; 5*64*144 = 46080
#define W3_OFF   (W2_OFF + 5 * 64 * RSB)           // 120960; 5*64*16  = 5120
#define D3_OFF   (W3_OFF + 5 * 64 * 16)            // 126080; 256*8*4  = 8192
#define MISC_OFF (D3_OFF + MTOT * 8 * 4)           // 134272
#define SMEM_DYN (MISC_OFF + 8192)                 // 142464 (139.1 KB)

// polynomial-accuracy constants (K=5, derivative=1, constraint_order=1)
#define AP0  0.0833333333333333f
#define AP1 -0.6666666666666667f
#define AP3  0.6666666666666667f
#define AP4 -0.0833333333333333f
#define NB_P0 -0.4472135954999579f
#define NB_S4 -0.1381966011250105f
#define DXH 0.0078125f
#define CFL 0.01f

__device__ float g_mn[4096];
__device__ float g_inv[4096];
__device__ __align__(16) unsigned char g_W2p[5 * 64 * RSB];  // bf16 [tap][ci][co pad 72]
__device__ __align__(16) unsigned char g_W3p[5 * 64 * 16];   // bf16 [tap][ci][co pad 8]

// ---------------------------------------------------------------------------
// helpers
// ---------------------------------------------------------------------------
__device__ __forceinline__ uint32_t smem_u32(const void* p) {
    uint32_t a;
    asm("{ .reg .u64 t; cvta.to.shared.u64 t, %1; cvt.u32.u64 %0, t; }" : "=r"(a) : "l"(p));
    return a;
}
__device__ __forceinline__ float tanha(float x) {
    float y; asm("tanh.approx.f32 %0, %1;" : "=f"(y) : "f"(x)); return y;
}
#define CVTBF2(res, lo, hi) \
    asm("cvt.rn.bf16x2.f32 %0, %1, %2;" : "=r"(res) : "f"(hi), "f"(lo))
#define STS128(a, r0, r1, r2, r3) \
    asm volatile("st.shared.v4.b32 [%0], {%1, %2, %3, %4};" :: "r"(a), "r"(r0), "r"(r1), "r"(r2), "r"(r3) : "memory")

__device__ __forceinline__ void ldsm_x4(uint32_t& r0, uint32_t& r1, uint32_t& r2,
                                        uint32_t& r3, uint32_t a) {
    asm volatile("ldmatrix.sync.aligned.m8n8.x4.shared.b16 {%0,%1,%2,%3}, [%4];"
                 : "=r"(r0), "=r"(r1), "=r"(r2), "=r"(r3) : "r"(a));
}
__device__ __forceinline__ void ldsm_x4t(uint32_t& r0, uint32_t& r1, uint32_t& r2,
                                         uint32_t& r3, uint32_t a) {
    asm volatile("ldmatrix.sync.aligned.m8n8.x4.trans.shared.b16 {%0,%1,%2,%3}, [%4];"
                 : "=r"(r0), "=r"(r1), "=r"(r2), "=r"(r3) : "r"(a));
}
__device__ __forceinline__ void ldsm_x2t(uint32_t& r0, uint32_t& r1, uint32_t a) {
    asm volatile("ldmatrix.sync.aligned.m8n8.x2.trans.shared.b16 {%0,%1}, [%2];"
                 : "=r"(r0), "=r"(r1) : "r"(a));
}
__device__ __forceinline__ void mma16816(float& c0, float& c1, float& c2, float& c3,
                                         uint32_t a0, uint32_t a1, uint32_t a2, uint32_t a3,
                                         uint32_t b0, uint32_t b1) {
    asm volatile("mma.sync.aligned.m16n8k16.row.col.f32.bf16.bf16.f32 "
                 "{%0,%1,%2,%3}, {%4,%5,%6,%7}, {%8,%9}, {%0,%1,%2,%3};"
                 : "+f"(c0), "+f"(c1), "+f"(c2), "+f"(c3)
                 : "r"(a0), "r"(a1), "r"(a2), "r"(a3), "r"(b0), "r"(b1));
}

// ---------------------------------------------------------------------------
// Prep kernel: blocks 0..B-1 -> per-row min/max; block B -> weight convert
// ---------------------------------------------------------------------------
__global__ void prep_kernel(const float* __restrict__ Prim,
                            const float* __restrict__ W2,
                            const float* __restrict__ W3, int B) {
    if ((int)blockIdx.x < B) {
        __shared__ float smx[32], smn[32];
        int b = blockIdx.x;
        const float4* P = reinterpret_cast<const float4*>(Prim + (size_t)b * LLEN);
        float mx = -3.402823466e38f, mn = 3.402823466e38f;
        for (int i = threadIdx.x; i < LLEN / 4; i += blockDim.x) {
            float4 v = P[i];
            mx = fmaxf(mx, fmaxf(fmaxf(v.x, v.y), fmaxf(v.z, v.w)));
            mn = fminf(mn, fminf(fminf(v.x, v.y), fminf(v.z, v.w)));
        }
        #pragma unroll
        for (int o = 16; o > 0; o >>= 1) {
            mx = fmaxf(mx, __shfl_xor_sync(0xffffffffu, mx, o));
            mn = fminf(mn, __shfl_xor_sync(0xffffffffu, mn, o));
        }
        int w = threadIdx.x >> 5;
        if ((threadIdx.x & 31) == 0) { smx[w] = mx; smn[w] = mn; }
        __syncthreads();
        if (threadIdx.x == 0) {
            int nw = blockDim.x >> 5;
            for (int i = 1; i < nw; i++) { mx = fmaxf(mx, smx[i]); mn = fminf(mn, smn[i]); }
            g_mn[b]  = mn;
            g_inv[b] = 1.0f / fmaxf((mx - mn) * 0.5f, 1e-4f);
        }
    } else {
        for (int idx = threadIdx.x; idx < 5 * 64 * 64; idx += blockDim.x) {
            int k = idx >> 12, ci = (idx >> 6) & 63, co = idx & 63;
            *reinterpret_cast<__nv_bfloat16*>(
                g_W2p + (k * 64 + ci) * RSB + co * 2) = __float2bfloat16(W2[idx]);
        }
        for (int idx = threadIdx.x; idx < 5 * 64 * 8; idx += blockDim.x) {
            int k = idx >> 9, ci = (idx >> 3) & 63, co = idx & 7;
            float f = (co < 4) ? W3[(k * 64 + ci) * 4 + co] : 0.0f;
            *reinterpret_cast<__nv_bfloat16*>(
                g_W3p + (k * 64 + ci) * 16 + co * 2) = __float2bfloat16(f);
        }
    }
}

// ---------------------------------------------------------------------------
// Persistent fused kernel
// ---------------------------------------------------------------------------
__global__ void __launch_bounds__(NTHREADS, 1)
fused_kernel(const float* __restrict__ Prim,
             const float* __restrict__ W1, const float* __restrict__ b1,
             const float* __restrict__ b2, const float* __restrict__ b3,
             float* __restrict__ Out, int NT, int GRID) {
    extern __shared__ char smc[];
    const uint32_t smb = smem_u32(smc);

    float* sD3  = (float*)(smc + D3_OFF);       // [256][8]
    float* sy   = (float*)(smc + MISC_OFF);     // 264
    float* sP   = sy + 264;                     // 264
    float* sg   = sP + 264;                     // 256 (252 used)
    float* sphi = sg + 256;                     // 256 (251 used)
    float* sW1  = sphi + 256;                   // 320
    float* sb1  = sW1 + 320;                    // 64
    float* sb2  = sb1 + 64;                     // 64
    float* sb3  = sb2 + 64;                     // 4

    const int tid  = threadIdx.x;
    const int wid  = tid >> 5;
    const int lane = tid & 31;

    // ---- one-time staging: weights ----
    {
        const int4* s2 = (const int4*)g_W2p;
        int4* d2 = (int4*)(smc + W2_OFF);
        for (int i = tid; i < 5 * 64 * RSB / 16; i += NTHREADS) d2[i] = s2[i];
        const int4* s3 = (const int4*)g_W3p;
        int4* d3 = (int4*)(smc + W3_OFF);
        for (int i = tid; i < 5 * 64; i += NTHREADS) d3[i] = s3[i];
    }
    if (tid < 320) sW1[tid] = W1[tid];
    if (tid < 64) { sb1[tid] = b1[tid]; sb2[tid] = b2[tid]; }
    if (tid < 4)  sb3[tid] = b3[tid];

    // ---- first tile halo ----
    int t0 = blockIdx.x;
    if (t0 < NT && tid < Y_N) {
        int b = t0 / NTILES, s = (t0 % NTILES) * TILE;
        float mnb = g_mn[b], invb = g_inv[b];
        float p = Prim[(size_t)b * LLEN + ((s + tid - 8 + LLEN) & (LLEN - 1))];
        sP[tid] = p;
        sy[tid] = (p - mnb) * invb - 1.0f;
    }
    __syncthreads();

    const int arow  = lane & 15;
    const int acolB = (lane >> 4) * 8;

    for (int t = t0; t < NT; t += GRID) {
        const int b = t / NTILES;
        const int s = (t % NTILES) * TILE;

        // ---- prefetch next tile's halo into a register ----
        int t2 = t + GRID;
        float pnext = 0.0f, mn2 = 0.0f, inv2 = 1.0f;
        const bool hn = (t2 < NT) && (tid < Y_N);
        if (hn) {
            int b2 = t2 / NTILES, s2 = (t2 % NTILES) * TILE;
            mn2 = g_mn[b2]; inv2 = g_inv[b2];
            pnext = Prim[(size_t)b2 * LLEN + ((s2 + tid - 8 + LLEN) & (LLEN - 1))];
        }

        // ---- conv1: y -> h1 bf16 [260][64] ----
        {
            int chunk = tid & 7;
            int rs    = tid >> 3;
            int c0    = chunk * 8;
            for (int m = rs; m < H1_ROWS; m += 64) {
                float y0 = sy[m], y1 = sy[m+1], y2 = sy[m+2], y3 = sy[m+3], y4 = sy[m+4];
                float h[8];
                #pragma unroll
                for (int j = 0; j < 8; j++) {
                    float acc = sb1[c0 + j];
                    acc = fmaf(sW1[c0 + j],       y0, acc);
                    acc = fmaf(sW1[64  + c0 + j], y1, acc);
                    acc = fmaf(sW1[128 + c0 + j], y2, acc);
                    acc = fmaf(sW1[192 + c0 + j], y3, acc);
                    acc = fmaf(sW1[256 + c0 + j], y4, acc);
                    h[j] = tanha(acc);
                }
                uint32_t pk[4];
                #pragma unroll
                for (int i = 0; i < 4; i++) CVTBF2(pk[i], h[2*i], h[2*i+1]);
                STS128(smb + H1_OFF + m * RSB + chunk * 16, pk[0], pk[1], pk[2], pk[3]);
            }
        }
        __syncthreads();

        // ---- conv2 via mma.sync: each warp one 16x64 stripe ----
        {
            const int r0 = wid * 16;
            float acc[8][4];
            #pragma unroll
            for (int u = 0; u < 8; u++)
                #pragma unroll
                for (int v = 0; v < 4; v++) acc[u][v] = 0.0f;

            #pragma unroll
            for (int tap = 0; tap < 5; tap++) {
                #pragma unroll
                for (int cc = 0; cc < 4; cc++) {
                    uint32_t a0, a1, a2, a3;
                    ldsm_x4(a0, a1, a2, a3,
                            smb + H1_OFF + (r0 + tap + arow) * RSB + (cc * 16 + acolB) * 2);
                    uint32_t wb = smb + W2_OFF + (tap * 64 + cc * 16 + arow) * RSB;
                    #pragma unroll
                    for (int nb = 0; nb < 4; nb++) {
                        uint32_t f0, f1, f2, f3;
                        ldsm_x4t(f0, f1, f2, f3, wb + (nb * 16 + acolB) * 2);
                        mma16816(acc[nb*2][0],   acc[nb*2][1],   acc[nb*2][2],   acc[nb*2][3],
                                 a0, a1, a2, a3, f0, f1);
                        mma16816(acc[nb*2+1][0], acc[nb*2+1][1], acc[nb*2+1][2], acc[nb*2+1][3],
                                 a0, a1, a2, a3, f2, f3);
                    }
                }
            }
            // epilogue: bias + tanh -> h2 bf16
            int rA = r0 + (lane >> 2);
            int colb = (lane & 3) * 2;
            #pragma unroll
            for (int u = 0; u < 8; u++) {
                int col = u * 8 + colb;
                float bL = sb2[col], bH = sb2[col + 1];
                uint32_t p0, p1;
                CVTBF2(p0, tanha(acc[u][0] + bL), tanha(acc[u][1] + bH));
                CVTBF2(p1, tanha(acc[u][2] + bL), tanha(acc[u][3] + bH));
                *(uint32_t*)(smc + H2_OFF + rA * RSB + col * 2) = p0;
                *(uint32_t*)(smc + H2_OFF + (rA + 8) * RSB + col * 2) = p1;
            }
        }
        __syncthreads();

        // ---- conv3 via mma.sync: each warp one 16x8 stripe ----
        {
            const int r0 = wid * 16;
            float acc[4] = {0.f, 0.f, 0.f, 0.f};
            #pragma unroll
            for (int tap = 0; tap < 5; tap++) {
                #pragma unroll
                for (int cc = 0; cc < 4; cc++) {
                    uint32_t a0, a1, a2, a3;
                    ldsm_x4(a0, a1, a2, a3,
                            smb + H2_OFF + (r0 + tap + arow) * RSB + (cc * 16 + acolB) * 2);
                    uint32_t f0, f1;
                    ldsm_x2t(f0, f1, smb + W3_OFF + (tap * 64 + cc * 16 + arow) * 16);
                    mma16816(acc[0], acc[1], acc[2], acc[3], a0, a1, a2, a3, f0, f1);
                }
            }
            int rA = r0 + (lane >> 2);
            int colb = (lane & 3) * 2;
            *(float2*)&sD3[rA * 8 + colb]       = make_float2(acc[0], acc[1]);
            *(float2*)&sD3[(rA + 8) * 8 + colb] = make_float2(acc[2], acc[3]);
        }
        __syncthreads();

        // ---- grad ----
        if (tid < G_N) {
            int ic = tid;
            float c0 = sD3[ic * 8 + 0] + sb3[0];
            float c1 = sD3[ic * 8 + 1] + sb3[1];
            float c2 = sD3[ic * 8 + 2] + sb3[2];
            float c3 = sD3[ic * 8 + 3] + sb3[3];
            float p0 = sP[ic + 4], p1 = sP[ic + 5], p2 = sP[ic + 6],
                  p3 = sP[ic + 7], p4 = sP[ic + 8];
            float dotp = AP0 * p0 + AP1 * p1 + AP3 * p3 + AP4 * p4;
            float S4   = p1 + p2 + p3 + p4;
            float base = NB_P0 * p0 + NB_S4 * S4;
            float corr = c0 * (base + p1) + c1 * (base + p2)
                       + c2 * (base + p3) + c3 * (base + p4);
            sg[ic] = (dotp + corr) * 64.0f;
        }
        __syncthreads();

        // ---- TVD limiter ----
        if (tid < PHI_N) {
            float gcur = sg[tid + 1];
            float gpre = sg[tid];
            float aa = (gcur < 0.0f) ? -1.0f : 1.0f;
            float ri = gpre / (fmaxf(fabsf(gcur), 1e-15f) * aa);
            sphi[tid] = (ri * ri + ri) / (ri * ri + 1.0f);
        }
        __syncthreads();

        // ---- Godunov flux + update + store ----
        if (tid < TILE) {
            int j = tid;
            float fl[2];
            #pragma unroll
            for (int u = 0; u < 2; u++) {
                int f = j - 1 + u;
                float uL = fmaf(DXH * sphi[f + 1], sg[f + 2], sP[f + 8]);
                float uR = fmaf(-DXH * sphi[f + 2], sg[f + 3], sP[f + 9]);
                fl[u] = 0.25f * (uL * uL + uR * uR)
                      - 0.25f * fabsf(uL + uR) * (uR - uL);
            }
            int gidx = (s + j) & (LLEN - 1);
            Out[(size_t)b * LLEN + gidx] = sP[j + 8] - CFL * (fl[1] - fl[0]);
        }
        __syncthreads();   // flux reads of sP done before halo overwrite

        // ---- commit prefetched halo for next iteration ----
        if (hn) {
            sP[tid] = pnext;
            sy[tid] = (pnext - mn2) * inv2 - 1.0f;
        }
        __syncthreads();
    }
}

// ---------------------------------------------------------------------------
// Launch (no statics, no device queries — graph-capture safe)
// ---------------------------------------------------------------------------
extern "C" void kernel_launch(void* const* d_in, const int* in_sizes, int n_in,
                              void* d_out, int out_size) {
    const float* Prim = (const float*)d_in[0];
    const float* W1   = (const float*)d_in[1];
    const float* b1   = (const float*)d_in[2];
    const float* W2   = (const float*)d_in[3];
    const float* b2   = (const float*)d_in[4];
    const float* W3   = (const float*)d_in[5];
    const float* b3   = (const float*)d_in[6];
    float* Out = (float*)d_out;

    int B  = in_sizes[0] / LLEN;
    int NT = B * NTILES;

    cudaFuncSetAttribute(fused_kernel,
                         cudaFuncAttributeMaxDynamicSharedMemorySize, SMEM_DYN);

    int grid = GRID_SM;
    if (grid > NT) grid = NT;

    prep_kernel<<<B + 1, 1024>>>(Prim, W2, W3, B);
    fused_kernel<<<grid, NTHREADS, SMEM_DYN>>>(
        Prim, W1, b1, b2, b3, Out, NT, grid);
}

// round 6
// speedup vs baseline: 5.4830x; 1.1202x over previous
#include <cuda_runtime.h>
#include <cuda_bf16.h>
#include <math.h>
#include <stdint.h>

// ---------------------------------------------------------------------------
// Problem constants: B=256, L=8192, K=5, C=64, CO=4
// ---------------------------------------------------------------------------
#define LLEN     8192
#define TILE     505         // output points per tile
#define NTILES   17          // ceil(8192/505); tail wraps (duplicate identical writes)
#define MTOT     512         // MMA M rows per tile
#define Y_N      520         // Prim/y halo rows: j in [-8, TILE+6]
#define H1_ROWS  516
#define H2_ROWS  516         // 512 computed + 4 garbage tail (read by last mma3 stripe)
#define G_N      508
#define PHI_N    507
#define NTHREADS 512
#define GRID_SM  148         // B200 sm_100a SM count

// bf16 row stride for h1/h2/W2: 72 elems = 144 B (9*16B -> conflict-free ldmatrix)
#define RSB      144

// smem byte layout
#define H1_OFF   0                                 // 516*144 = 74304
#define H2_OFF   (H1_OFF + H1_ROWS * RSB)          // 74304
#define W2_OFF   (H2_OFF + H2_ROWS * RSB)          // 148608 ; 5*64*144 = 46080
#define W3_OFF   (W2_OFF + 5 * 64 * RSB)           // 194688 ; 5*64*16  = 5120
#define D3_OFF   (W3_OFF + 5 * 64 * 16)            // 199808 ; 512*8*4  = 16384
#define MISC_OFF (D3_OFF + MTOT * 8 * 4)           // 216192
#define SMEM_DYN (MISC_OFF + 10240)                // 226432 (221.1 KB) < 227 KB opt-in

// polynomial-accuracy constants (K=5, derivative=1, constraint_order=1)
#define AP0  0.0833333333333333f
#define AP1 -0.6666666666666667f
#define AP3  0.6666666666666667f
#define AP4 -0.0833333333333333f
#define NB_P0 -0.4472135954999579f
#define NB_S4 -0.1381966011250105f
#define DXH 0.0078125f
#define CFL 0.01f

__device__ float g_mn[4096];
__device__ float g_inv[4096];
__device__ __align__(16) unsigned char g_W2p[5 * 64 * RSB];  // bf16 [tap][ci][co pad 72]
__device__ __align__(16) unsigned char g_W3p[5 * 64 * 16];   // bf16 [tap][ci][co pad 8]

// ---------------------------------------------------------------------------
// helpers
// ---------------------------------------------------------------------------
__device__ __forceinline__ uint32_t smem_u32(const void* p) {
    uint32_t a;
    asm("{ .reg .u64 t; cvta.to.shared.u64 t, %1; cvt.u32.u64 %0, t; }" : "=r"(a) : "l"(p));
    return a;
}
__device__ __forceinline__ float tanha(float x) {
    float y; asm("tanh.approx.f32 %0, %1;" : "=f"(y) : "f"(x)); return y;
}
#define CVTBF2(res, lo, hi) \
    asm("cvt.rn.bf16x2.f32 %0, %1, %2;" : "=r"(res) : "f"(hi), "f"(lo))
#define STS128(a, r0, r1, r2, r3) \
    asm volatile("st.shared.v4.b32 [%0], {%1, %2, %3, %4};" :: "r"(a), "r"(r0), "r"(r1), "r"(r2), "r"(r3) : "memory")

__device__ __forceinline__ void ldsm_x4(uint32_t& r0, uint32_t& r1, uint32_t& r2,
                                        uint32_t& r3, uint32_t a) {
    asm volatile("ldmatrix.sync.aligned.m8n8.x4.shared.b16 {%0,%1,%2,%3}, [%4];"
                 : "=r"(r0), "=r"(r1), "=r"(r2), "=r"(r3) : "r"(a));
}
__device__ __forceinline__ void ldsm_x4t(uint32_t& r0, uint32_t& r1, uint32_t& r2,
                                         uint32_t& r3, uint32_t a) {
    asm volatile("ldmatrix.sync.aligned.m8n8.x4.trans.shared.b16 {%0,%1,%2,%3}, [%4];"
                 : "=r"(r0), "=r"(r1), "=r"(r2), "=r"(r3) : "r"(a));
}
__device__ __forceinline__ void ldsm_x2t(uint32_t& r0, uint32_t& r1, uint32_t a) {
    asm volatile("ldmatrix.sync.aligned.m8n8.x2.trans.shared.b16 {%0,%1}, [%2];"
                 : "=r"(r0), "=r"(r1) : "r"(a));
}
__device__ __forceinline__ void mma16816(float& c0, float& c1, float& c2, float& c3,
                                         uint32_t a0, uint32_t a1, uint32_t a2, uint32_t a3,
                                         uint32_t b0, uint32_t b1) {
    asm volatile("mma.sync.aligned.m16n8k16.row.col.f32.bf16.bf16.f32 "
                 "{%0,%1,%2,%3}, {%4,%5,%6,%7}, {%8,%9}, {%0,%1,%2,%3};"
                 : "+f"(c0), "+f"(c1), "+f"(c2), "+f"(c3)
                 : "r"(a0), "r"(a1), "r"(a2), "r"(a3), "r"(b0), "r"(b1));
}

// ---------------------------------------------------------------------------
// Prep kernel: blocks 0..B-1 -> per-row min/max; block B -> weight convert
// ---------------------------------------------------------------------------
__global__ void prep_kernel(const float* __restrict__ Prim,
                            const float* __restrict__ W2,
                            const float* __restrict__ W3, int B) {
    if ((int)blockIdx.x < B) {
        __shared__ float smx[32], smn[32];
        int b = blockIdx.x;
        const float4* P = reinterpret_cast<const float4*>(Prim + (size_t)b * LLEN);
        float mx = -3.402823466e38f, mn = 3.402823466e38f;
        for (int i = threadIdx.x; i < LLEN / 4; i += blockDim.x) {
            float4 v = P[i];
            mx = fmaxf(mx, fmaxf(fmaxf(v.x, v.y), fmaxf(v.z, v.w)));
            mn = fminf(mn, fminf(fminf(v.x, v.y), fminf(v.z, v.w)));
        }
        #pragma unroll
        for (int o = 16; o > 0; o >>= 1) {
            mx = fmaxf(mx, __shfl_xor_sync(0xffffffffu, mx, o));
            mn = fminf(mn, __shfl_xor_sync(0xffffffffu, mn, o));
        }
        int w = threadIdx.x >> 5;
        if ((threadIdx.x & 31) == 0) { smx[w] = mx; smn[w] = mn; }
        __syncthreads();
        if (threadIdx.x == 0) {
            int nw = blockDim.x >> 5;
            for (int i = 1; i < nw; i++) { mx = fmaxf(mx, smx[i]); mn = fminf(mn, smn[i]); }
            g_mn[b]  = mn;
            g_inv[b] = 1.0f / fmaxf((mx - mn) * 0.5f, 1e-4f);
        }
    } else {
        for (int idx = threadIdx.x; idx < 5 * 64 * 64; idx += blockDim.x) {
            int k = idx >> 12, ci = (idx >> 6) & 63, co = idx & 63;
            *reinterpret_cast<__nv_bfloat16*>(
                g_W2p + (k * 64 + ci) * RSB + co * 2) = __float2bfloat16(W2[idx]);
        }
        for (int idx = threadIdx.x; idx < 5 * 64 * 8; idx += blockDim.x) {
            int k = idx >> 9, ci = (idx >> 3) & 63, co = idx & 7;
            float f = (co < 4) ? W3[(k * 64 + ci) * 4 + co] : 0.0f;
            *reinterpret_cast<__nv_bfloat16*>(
                g_W3p + (k * 64 + ci) * 16 + co * 2) = __float2bfloat16(f);
        }
    }
}

// ---------------------------------------------------------------------------
// Persistent fused kernel: warp tile 32m x 64n (B fragments amortized 2x)
// ---------------------------------------------------------------------------
__global__ void __launch_bounds__(NTHREADS, 1)
fused_kernel(const float* __restrict__ Prim,
             const float* __restrict__ W1, const float* __restrict__ b1,
             const float* __restrict__ b2, const float* __restrict__ b3,
             float* __restrict__ Out, int NT, int GRID) {
    extern __shared__ char smc[];
    const uint32_t smb = smem_u32(smc);

    float* sD3  = (float*)(smc + D3_OFF);       // [512][8]
    float* sy   = (float*)(smc + MISC_OFF);     // 520
    float* sP   = sy + 520;                     // 520
    float* sg   = sP + 520;                     // 512 (508 used)
    float* sphi = sg + 512;                     // 512 (507 used)
    float* sW1  = sphi + 512;                   // 320
    float* sb1  = sW1 + 320;                    // 64
    float* sb2  = sb1 + 64;                     // 64
    float* sb3  = sb2 + 64;                     // 4

    const int tid  = threadIdx.x;
    const int wid  = tid >> 5;
    const int lane = tid & 31;

    // ---- one-time staging: weights ----
    {
        const int4* s2 = (const int4*)g_W2p;
        int4* d2 = (int4*)(smc + W2_OFF);
        for (int i = tid; i < 5 * 64 * RSB / 16; i += NTHREADS) d2[i] = s2[i];
        const int4* s3 = (const int4*)g_W3p;
        int4* d3 = (int4*)(smc + W3_OFF);
        for (int i = tid; i < 5 * 64; i += NTHREADS) d3[i] = s3[i];
    }
    if (tid < 320) sW1[tid] = W1[tid];
    if (tid < 64) { sb1[tid] = b1[tid]; sb2[tid] = b2[tid]; }
    if (tid < 4)  sb3[tid] = b3[tid];

    // ---- first tile halo ----
    int t0 = blockIdx.x;
    if (t0 < NT) {
        int b = t0 / NTILES, s = (t0 % NTILES) * TILE;
        float mnb = g_mn[b], invb = g_inv[b];
        for (int i = tid; i < Y_N; i += NTHREADS) {
            float p = Prim[(size_t)b * LLEN + ((s + i - 8 + LLEN) & (LLEN - 1))];
            sP[i] = p;
            sy[i] = (p - mnb) * invb - 1.0f;
        }
    }
    __syncthreads();

    const int arow  = lane & 15;
    const int acolB = (lane >> 4) * 8;

    for (int t = t0; t < NT; t += GRID) {
        const int b = t / NTILES;
        const int s = (t % NTILES) * TILE;

        // ---- prefetch next tile's halo into registers ----
        int t2 = t + GRID;
        float pn0 = 0.0f, pn1 = 0.0f, mn2 = 0.0f, inv2 = 1.0f;
        const bool hn = (t2 < NT);
        if (hn) {
            int b2 = t2 / NTILES, s2 = (t2 % NTILES) * TILE;
            mn2 = g_mn[b2]; inv2 = g_inv[b2];
            const float* P2 = Prim + (size_t)b2 * LLEN;
            pn0 = P2[(s2 + tid - 8 + LLEN) & (LLEN - 1)];
            if (tid < Y_N - NTHREADS)
                pn1 = P2[(s2 + tid + NTHREADS - 8 + LLEN) & (LLEN - 1)];
        }

        // ---- conv1: y -> h1 bf16 [516][64] ----
        {
            int chunk = tid & 7;
            int rs    = tid >> 3;
            int c0    = chunk * 8;
            for (int m = rs; m < H1_ROWS; m += 64) {
                float y0 = sy[m], y1 = sy[m+1], y2 = sy[m+2], y3 = sy[m+3], y4 = sy[m+4];
                float h[8];
                #pragma unroll
                for (int j = 0; j < 8; j++) {
                    float acc = sb1[c0 + j];
                    acc = fmaf(sW1[c0 + j],       y0, acc);
                    acc = fmaf(sW1[64  + c0 + j], y1, acc);
                    acc = fmaf(sW1[128 + c0 + j], y2, acc);
                    acc = fmaf(sW1[192 + c0 + j], y3, acc);
                    acc = fmaf(sW1[256 + c0 + j], y4, acc);
                    h[j] = tanha(acc);
                }
                uint32_t pk[4];
                #pragma unroll
                for (int i = 0; i < 4; i++) CVTBF2(pk[i], h[2*i], h[2*i+1]);
                STS128(smb + H1_OFF + m * RSB + chunk * 16, pk[0], pk[1], pk[2], pk[3]);
            }
        }
        __syncthreads();

        // ---- conv2 via mma.sync: warp tile 32m x 64n ----
        {
            const int r0 = wid * 32;
            float acc[2][8][4];
            #pragma unroll
            for (int ss = 0; ss < 2; ss++)
                #pragma unroll
                for (int u = 0; u < 8; u++)
                    #pragma unroll
                    for (int v = 0; v < 4; v++) acc[ss][u][v] = 0.0f;

            #pragma unroll
            for (int tap = 0; tap < 5; tap++) {
                #pragma unroll
                for (int cc = 0; cc < 4; cc++) {
                    uint32_t a0, a1, a2, a3, e0, e1, e2, e3;
                    uint32_t abase = smb + H1_OFF + (r0 + tap + arow) * RSB
                                   + (cc * 16 + acolB) * 2;
                    ldsm_x4(a0, a1, a2, a3, abase);
                    ldsm_x4(e0, e1, e2, e3, abase + 16 * RSB);
                    uint32_t wb = smb + W2_OFF + (tap * 64 + cc * 16 + arow) * RSB;
                    #pragma unroll
                    for (int nb = 0; nb < 4; nb++) {
                        uint32_t f0, f1, f2, f3;
                        ldsm_x4t(f0, f1, f2, f3, wb + (nb * 16 + acolB) * 2);
                        mma16816(acc[0][nb*2][0],   acc[0][nb*2][1],   acc[0][nb*2][2],   acc[0][nb*2][3],
                                 a0, a1, a2, a3, f0, f1);
                        mma16816(acc[0][nb*2+1][0], acc[0][nb*2+1][1], acc[0][nb*2+1][2], acc[0][nb*2+1][3],
                                 a0, a1, a2, a3, f2, f3);
                        mma16816(acc[1][nb*2][0],   acc[1][nb*2][1],   acc[1][nb*2][2],   acc[1][nb*2][3],
                                 e0, e1, e2, e3, f0, f1);
                        mma16816(acc[1][nb*2+1][0], acc[1][nb*2+1][1], acc[1][nb*2+1][2], acc[1][nb*2+1][3],
                                 e0, e1, e2, e3, f2, f3);
                    }
                }
            }
            // epilogue: bias + tanh -> h2 bf16
            int colb = (lane & 3) * 2;
            #pragma unroll
            for (int ss = 0; ss < 2; ss++) {
                int rA = r0 + ss * 16 + (lane >> 2);
                #pragma unroll
                for (int u = 0; u < 8; u++) {
                    int col = u * 8 + colb;
                    float bL = sb2[col], bH = sb2[col + 1];
                    uint32_t p0, p1;
                    CVTBF2(p0, tanha(acc[ss][u][0] + bL), tanha(acc[ss][u][1] + bH));
                    CVTBF2(p1, tanha(acc[ss][u][2] + bL), tanha(acc[ss][u][3] + bH));
                    *(uint32_t*)(smc + H2_OFF + rA * RSB + col * 2) = p0;
                    *(uint32_t*)(smc + H2_OFF + (rA + 8) * RSB + col * 2) = p1;
                }
            }
        }
        __syncthreads();

        // ---- conv3 via mma.sync: warp tile 32m x 8n ----
        {
            const int r0 = wid * 32;
            float acc[2][4];
            #pragma unroll
            for (int ss = 0; ss < 2; ss++)
                #pragma unroll
                for (int v = 0; v < 4; v++) acc[ss][v] = 0.0f;
            #pragma unroll
            for (int tap = 0; tap < 5; tap++) {
                #pragma unroll
                for (int cc = 0; cc < 4; cc++) {
                    uint32_t a0, a1, a2, a3, e0, e1, e2, e3;
                    uint32_t abase = smb + H2_OFF + (r0 + tap + arow) * RSB
                                   + (cc * 16 + acolB) * 2;
                    ldsm_x4(a0, a1, a2, a3, abase);
                    ldsm_x4(e0, e1, e2, e3, abase + 16 * RSB);
                    uint32_t f0, f1;
                    ldsm_x2t(f0, f1, smb + W3_OFF + (tap * 64 + cc * 16 + arow) * 16);
                    mma16816(acc[0][0], acc[0][1], acc[0][2], acc[0][3], a0, a1, a2, a3, f0, f1);
                    mma16816(acc[1][0], acc[1][1], acc[1][2], acc[1][3], e0, e1, e2, e3, f0, f1);
                }
            }
            int colb = (lane & 3) * 2;
            #pragma unroll
            for (int ss = 0; ss < 2; ss++) {
                int rA = r0 + ss * 16 + (lane >> 2);
                *(float2*)&sD3[rA * 8 + colb]       = make_float2(acc[ss][0], acc[ss][1]);
                *(float2*)&sD3[(rA + 8) * 8 + colb] = make_float2(acc[ss][2], acc[ss][3]);
            }
        }
        __syncthreads();

        // ---- grad ----
        if (tid < G_N) {
            int ic = tid;
            float c0 = sD3[ic * 8 + 0] + sb3[0];
            float c1 = sD3[ic * 8 + 1] + sb3[1];
            float c2 = sD3[ic * 8 + 2] + sb3[2];
            float c3 = sD3[ic * 8 + 3] + sb3[3];
            float p0 = sP[ic + 4], p1 = sP[ic + 5], p2 = sP[ic + 6],
                  p3 = sP[ic + 7], p4 = sP[ic + 8];
            float dotp = AP0 * p0 + AP1 * p1 + AP3 * p3 + AP4 * p4;
            float S4   = p1 + p2 + p3 + p4;
            float base = NB_P0 * p0 + NB_S4 * S4;
            float corr = c0 * (base + p1) + c1 * (base + p2)
                       + c2 * (base + p3) + c3 * (base + p4);
            sg[ic] = (dotp + corr) * 64.0f;
        }
        __syncthreads();

        // ---- TVD limiter ----
        if (tid < PHI_N) {
            float gcur = sg[tid + 1];
            float gpre = sg[tid];
            float aa = (gcur < 0.0f) ? -1.0f : 1.0f;
            float ri = gpre / (fmaxf(fabsf(gcur), 1e-15f) * aa);
            sphi[tid] = (ri * ri + ri) / (ri * ri + 1.0f);
        }
        __syncthreads();

        // ---- Godunov flux + update + store ----
        if (tid < TILE) {
            int j = tid;
            float fl[2];
            #pragma unroll
            for (int u = 0; u < 2; u++) {
                int f = j - 1 + u;
                float uL = fmaf(DXH * sphi[f + 1], sg[f + 2], sP[f + 8]);
                float uR = fmaf(-DXH * sphi[f + 2], sg[f + 3], sP[f + 9]);
                fl[u] = 0.25f * (uL * uL + uR * uR)
                      - 0.25f * fabsf(uL + uR) * (uR - uL);
            }
            int gidx = (s + j) & (LLEN - 1);
            Out[(size_t)b * LLEN + gidx] = sP[j + 8] - CFL * (fl[1] - fl[0]);
        }
        __syncthreads();   // flux reads of sP done before halo overwrite

        // ---- commit prefetched halo ----
        if (hn) {
            sP[tid] = pn0;
            sy[tid] = (pn0 - mn2) * inv2 - 1.0f;
            if (tid < Y_N - NTHREADS) {
                sP[tid + NTHREADS] = pn1;
                sy[tid + NTHREADS] = (pn1 - mn2) * inv2 - 1.0f;
            }
        }
        __syncthreads();
    }
}

// ---------------------------------------------------------------------------
// Launch (no statics, no device queries — graph-capture safe)
// ---------------------------------------------------------------------------
extern "C" void kernel_launch(void* const* d_in, const int* in_sizes, int n_in,
                              void* d_out, int out_size) {
    const float* Prim = (const float*)d_in[0];
    const float* W1   = (const float*)d_in[1];
    const float* b1   = (const float*)d_in[2];
    const float* W2   = (const float*)d_in[3];
    const float* b2   = (const float*)d_in[4];
    const float* W3   = (const float*)d_in[5];
    const float* b3   = (const float*)d_in[6];
    float* Out = (float*)d_out;

    int B  = in_sizes[0] / LLEN;
    int NT = B * NTILES;

    cudaFuncSetAttribute(fused_kernel,
                         cudaFuncAttributeMaxDynamicSharedMemorySize, SMEM_DYN);

    int grid = GRID_SM;
    if (grid > NT) grid = NT;

    prep_kernel<<<B + 1, 1024>>>(Prim, W2, W3, B);
    fused_kernel<<<grid, NTHREADS, SMEM_DYN>>>(
        Prim, W1, b1, b2, b3, Out, NT, grid);
}

// round 9
// speedup vs baseline: 5.6212x; 1.0252x over previous
#include <cuda_runtime.h>
#include <cuda_bf16.h>
#include <math.h>
#include <stdint.h>

// ---------------------------------------------------------------------------
// Problem constants: B=256, L=8192, K=5, C=64, CO=4
// ---------------------------------------------------------------------------
#define LLEN     8192
#define TILE     505         // output points per tile
#define NTILES   17          // ceil(8192/505); tail wraps (duplicate identical writes)
#define MTOT     512         // MMA M rows per tile
#define Y_N      520         // Prim/y halo rows: j in [-8, TILE+6]
#define H1_ROWS  516
#define H2_ROWS  516         // 512 computed + 4 garbage tail (read by last mma3 stripe)
#define G_N      508
#define PHI_N    507
#define NTHREADS 256         // 8 warps; warp conv2 tile = 64m x 64n
#define GRID_SM  148         // B200 sm_100a SM count

// bf16 row stride for h1/h2/W2: 72 elems = 144 B (9*16B -> conflict-free ldmatrix)
#define RSB      144

// smem byte layout
#define H1_OFF   0                                 // 516*144 = 74304
#define H2_OFF   (H1_OFF + H1_ROWS * RSB)          // 74304
#define W2_OFF   (H2_OFF + H2_ROWS * RSB)          // 148608 ; 5*64*144 = 46080
#define W3_OFF   (W2_OFF + 5 * 64 * RSB)           // 194688 ; 5*64*16  = 5120
#define D3_OFF   (W3_OFF + 5 * 64 * 16)            // 199808 ; 512*8*4  = 16384
#define MISC_OFF (D3_OFF + MTOT * 8 * 4)           // 216192
#define SMEM_DYN (MISC_OFF + 10240)                // 226432 (221.1 KB) < 227 KB opt-in

// polynomial-accuracy constants (K=5, derivative=1, constraint_order=1)
#define AP0  0.0833333333333333f
#define AP1 -0.6666666666666667f
#define AP3  0.6666666666666667f
#define AP4 -0.0833333333333333f
#define NB_P0 -0.4472135954999579f
#define NB_S4 -0.1381966011250105f
#define DXH 0.0078125f
#define CFL 0.01f

__device__ float g_mn[4096];
__device__ float g_inv[4096];
__device__ __align__(16) unsigned char g_W2p[5 * 64 * RSB];  // bf16 [tap][ci][co pad 72]
__device__ __align__(16) unsigned char g_W3p[5 * 64 * 16];   // bf16 [tap][ci][co pad 8]

// ---------------------------------------------------------------------------
// helpers
// ---------------------------------------------------------------------------
__device__ __forceinline__ uint32_t smem_u32(const void* p) {
    uint32_t a;
    asm("{ .reg .u64 t; cvta.to.shared.u64 t, %1; cvt.u32.u64 %0, t; }" : "=r"(a) : "l"(p));
    return a;
}
__device__ __forceinline__ float tanha(float x) {
    float y; asm("tanh.approx.f32 %0, %1;" : "=f"(y) : "f"(x)); return y;
}
#define CVTBF2(res, lo, hi) \
    asm("cvt.rn.bf16x2.f32 %0, %1, %2;" : "=r"(res) : "f"(hi), "f"(lo))
#define STS128(a, r0, r1, r2, r3) \
    asm volatile("st.shared.v4.b32 [%0], {%1, %2, %3, %4};" :: "r"(a), "r"(r0), "r"(r1), "r"(r2), "r"(r3) : "memory")

__device__ __forceinline__ void ldsm_x4(uint32_t& r0, uint32_t& r1, uint32_t& r2,
                                        uint32_t& r3, uint32_t a) {
    asm volatile("ldmatrix.sync.aligned.m8n8.x4.shared.b16 {%0,%1,%2,%3}, [%4];"
                 : "=r"(r0), "=r"(r1), "=r"(r2), "=r"(r3) : "r"(a));
}
__device__ __forceinline__ void ldsm_x4t(uint32_t& r0, uint32_t& r1, uint32_t& r2,
                                         uint32_t& r3, uint32_t a) {
    asm volatile("ldmatrix.sync.aligned.m8n8.x4.trans.shared.b16 {%0,%1,%2,%3}, [%4];"
                 : "=r"(r0), "=r"(r1), "=r"(r2), "=r"(r3) : "r"(a));
}
__device__ __forceinline__ void ldsm_x2t(uint32_t& r0, uint32_t& r1, uint32_t a) {
    asm volatile("ldmatrix.sync.aligned.m8n8.x2.trans.shared.b16 {%0,%1}, [%2];"
                 : "=r"(r0), "=r"(r1) : "r"(a));
}
__device__ __forceinline__ void mma16816(float& c0, float& c1, float& c2, float& c3,
                                         uint32_t a0, uint32_t a1, uint32_t a2, uint32_t a3,
                                         uint32_t b0, uint32_t b1) {
    asm volatile("mma.sync.aligned.m16n8k16.row.col.f32.bf16.bf16.f32 "
                 "{%0,%1,%2,%3}, {%4,%5,%6,%7}, {%8,%9}, {%0,%1,%2,%3};"
                 : "+f"(c0), "+f"(c1), "+f"(c2), "+f"(c3)
                 : "r"(a0), "r"(a1), "r"(a2), "r"(a3), "r"(b0), "r"(b1));
}

// ---------------------------------------------------------------------------
// Prep kernel: blocks 0..B-1 -> per-row min/max; block B -> weight convert
// ---------------------------------------------------------------------------
__global__ void prep_kernel(const float* __restrict__ Prim,
                            const float* __restrict__ W2,
                            const float* __restrict__ W3, int B) {
    if ((int)blockIdx.x < B) {
        __shared__ float smx[32], smn[32];
        int b = blockIdx.x;
        const float4* P = reinterpret_cast<const float4*>(Prim + (size_t)b * LLEN);
        float mx = -3.402823466e38f, mn = 3.402823466e38f;
        for (int i = threadIdx.x; i < LLEN / 4; i += blockDim.x) {
            float4 v = P[i];
            mx = fmaxf(mx, fmaxf(fmaxf(v.x, v.y), fmaxf(v.z, v.w)));
            mn = fminf(mn, fminf(fminf(v.x, v.y), fminf(v.z, v.w)));
        }
        #pragma unroll
        for (int o = 16; o > 0; o >>= 1) {
            mx = fmaxf(mx, __shfl_xor_sync(0xffffffffu, mx, o));
            mn = fminf(mn, __shfl_xor_sync(0xffffffffu, mn, o));
        }
        int w = threadIdx.x >> 5;
        if ((threadIdx.x & 31) == 0) { smx[w] = mx; smn[w] = mn; }
        __syncthreads();
        if (threadIdx.x == 0) {
            int nw = blockDim.x >> 5;
            for (int i = 1; i < nw; i++) { mx = fmaxf(mx, smx[i]); mn = fminf(mn, smn[i]); }
            g_mn[b]  = mn;
            g_inv[b] = 1.0f / fmaxf((mx - mn) * 0.5f, 1e-4f);
        }
    } else {
        for (int idx = threadIdx.x; idx < 5 * 64 * 64; idx += blockDim.x) {
            int k = idx >> 12, ci = (idx >> 6) & 63, co = idx & 63;
            *reinterpret_cast<__nv_bfloat16*>(
                g_W2p + (k * 64 + ci) * RSB + co * 2) = __float2bfloat16(W2[idx]);
        }
        for (int idx = threadIdx.x; idx < 5 * 64 * 8; idx += blockDim.x) {
            int k = idx >> 9, ci = (idx >> 3) & 63, co = idx & 7;
            float f = (co < 4) ? W3[(k * 64 + ci) * 4 + co] : 0.0f;
            *reinterpret_cast<__nv_bfloat16*>(
                g_W3p + (k * 64 + ci) * 16 + co * 2) = __float2bfloat16(f);
        }
    }
}

// ---------------------------------------------------------------------------
// Persistent fused kernel: 8 warps, conv2 warp tile 64m x 64n (B amortized 4x)
// ---------------------------------------------------------------------------
__global__ void __launch_bounds__(NTHREADS, 1)
fused_kernel(const float* __restrict__ Prim,
             const float* __restrict__ W1, const float* __restrict__ b1,
             const float* __restrict__ b2, const float* __restrict__ b3,
             float* __restrict__ Out, int NT, int GRID) {
    extern __shared__ char smc[];
    const uint32_t smb = smem_u32(smc);

    float* sD3  = (float*)(smc + D3_OFF);       // [512][8]
    float* sy   = (float*)(smc + MISC_OFF);     // 520
    float* sP   = sy + 520;                     // 520
    float* sg   = sP + 520;                     // 512 (508 used)
    float* sphi = sg + 512;                     // 512 (507 used)
    float* sW1  = sphi + 512;                   // 320
    float* sb1  = sW1 + 320;                    // 64
    float* sb2  = sb1 + 64;                     // 64
    float* sb3  = sb2 + 64;                     // 4

    const int tid  = threadIdx.x;
    const int wid  = tid >> 5;
    const int lane = tid & 31;

    // ---- one-time staging: weights ----
    {
        const int4* s2 = (const int4*)g_W2p;
        int4* d2 = (int4*)(smc + W2_OFF);
        for (int i = tid; i < 5 * 64 * RSB / 16; i += NTHREADS) d2[i] = s2[i];
        const int4* s3 = (const int4*)g_W3p;
        int4* d3 = (int4*)(smc + W3_OFF);
        for (int i = tid; i < 5 * 64; i += NTHREADS) d3[i] = s3[i];
    }
    for (int i = tid; i < 320; i += NTHREADS) sW1[i] = W1[i];
    if (tid < 64) { sb1[tid] = b1[tid]; sb2[tid] = b2[tid]; }
    if (tid < 4)  sb3[tid] = b3[tid];

    // ---- first tile halo ----
    int t0 = blockIdx.x;
    if (t0 < NT) {
        int b = t0 / NTILES, s = (t0 % NTILES) * TILE;
        float mnb = g_mn[b], invb = g_inv[b];
        for (int i = tid; i < Y_N; i += NTHREADS) {
            float p = Prim[(size_t)b * LLEN + ((s + i - 8 + LLEN) & (LLEN - 1))];
            sP[i] = p;
            sy[i] = (p - mnb) * invb - 1.0f;
        }
    }
    __syncthreads();

    const int arow  = lane & 15;
    const int acolB = (lane >> 4) * 8;

    for (int t = t0; t < NT; t += GRID) {
        const int b = t / NTILES;
        const int s = (t % NTILES) * TILE;

        // ---- prefetch next tile's halo into registers ----
        int t2 = t + GRID;
        float pn[3] = {0.f, 0.f, 0.f};
        float mn2 = 0.0f, inv2 = 1.0f;
        const bool hn = (t2 < NT);
        if (hn) {
            int b2 = t2 / NTILES, s2 = (t2 % NTILES) * TILE;
            mn2 = g_mn[b2]; inv2 = g_inv[b2];
            const float* P2 = Prim + (size_t)b2 * LLEN;
            #pragma unroll
            for (int k = 0; k < 3; k++) {
                int idx = tid + k * NTHREADS;
                if (idx < Y_N)
                    pn[k] = P2[(s2 + idx - 8 + LLEN) & (LLEN - 1)];
            }
        }

        // ---- conv1: y -> h1 bf16 [516][64] ----
        {
            int chunk = tid & 7;
            int rs    = tid >> 3;        // 0..31
            int c0    = chunk * 8;
            for (int m = rs; m < H1_ROWS; m += 32) {
                float y0 = sy[m], y1 = sy[m+1], y2 = sy[m+2], y3 = sy[m+3], y4 = sy[m+4];
                float h[8];
                #pragma unroll
                for (int j = 0; j < 8; j++) {
                    float acc = sb1[c0 + j];
                    acc = fmaf(sW1[c0 + j],       y0, acc);
                    acc = fmaf(sW1[64  + c0 + j], y1, acc);
                    acc = fmaf(sW1[128 + c0 + j], y2, acc);
                    acc = fmaf(sW1[192 + c0 + j], y3, acc);
                    acc = fmaf(sW1[256 + c0 + j], y4, acc);
                    h[j] = tanha(acc);
                }
                uint32_t pk[4];
                #pragma unroll
                for (int i = 0; i < 4; i++) CVTBF2(pk[i], h[2*i], h[2*i+1]);
                STS128(smb + H1_OFF + m * RSB + chunk * 16, pk[0], pk[1], pk[2], pk[3]);
            }
        }
        __syncthreads();

        // ---- conv2 via mma.sync: warp tile 64m x 64n ----
        {
            const int r0 = wid * 64;
            float acc[4][8][4];
            #pragma unroll
            for (int ss = 0; ss < 4; ss++)
                #pragma unroll
                for (int u = 0; u < 8; u++)
                    #pragma unroll
                    for (int v = 0; v < 4; v++) acc[ss][u][v] = 0.0f;

            #pragma unroll
            for (int tap = 0; tap < 5; tap++) {
                #pragma unroll
                for (int cc = 0; cc < 4; cc++) {
                    // B fragments for all 4 n-blocks (16 regs), reused by 4 m-stripes
                    uint32_t bf[4][4];
                    uint32_t wb = smb + W2_OFF + (tap * 64 + cc * 16 + arow) * RSB;
                    #pragma unroll
                    for (int nb = 0; nb < 4; nb++)
                        ldsm_x4t(bf[nb][0], bf[nb][1], bf[nb][2], bf[nb][3],
                                 wb + (nb * 16 + acolB) * 2);
                    #pragma unroll
                    for (int ss = 0; ss < 4; ss++) {
                        uint32_t a0, a1, a2, a3;
                        ldsm_x4(a0, a1, a2, a3,
                                smb + H1_OFF + (r0 + ss * 16 + tap + arow) * RSB
                                    + (cc * 16 + acolB) * 2);
                        #pragma unroll
                        for (int nb = 0; nb < 4; nb++) {
                            mma16816(acc[ss][nb*2][0],   acc[ss][nb*2][1],
                                     acc[ss][nb*2][2],   acc[ss][nb*2][3],
                                     a0, a1, a2, a3, bf[nb][0], bf[nb][1]);
                            mma16816(acc[ss][nb*2+1][0], acc[ss][nb*2+1][1],
                                     acc[ss][nb*2+1][2], acc[ss][nb*2+1][3],
                                     a0, a1, a2, a3, bf[nb][2], bf[nb][3]);
                        }
                    }
                }
            }
            // epilogue: bias + tanh -> h2 bf16
            int colb = (lane & 3) * 2;
            #pragma unroll
            for (int ss = 0; ss < 4; ss++) {
                int rA = r0 + ss * 16 + (lane >> 2);
                #pragma unroll
                for (int u = 0; u < 8; u++) {
                    int col = u * 8 + colb;
                    float bL = sb2[col], bH = sb2[col + 1];
                    uint32_t p0, p1;
                    CVTBF2(p0, tanha(acc[ss][u][0] + bL), tanha(acc[ss][u][1] + bH));
                    CVTBF2(p1, tanha(acc[ss][u][2] + bL), tanha(acc[ss][u][3] + bH));
                    *(uint32_t*)(smc + H2_OFF + rA * RSB + col * 2) = p0;
                    *(uint32_t*)(smc + H2_OFF + (rA + 8) * RSB + col * 2) = p1;
                }
            }
        }
        __syncthreads();

        // ---- conv3 via mma.sync: warp tile 64m x 8n ----
        {
            const int r0 = wid * 64;
            float acc3[4][4];
            #pragma unroll
            for (int ss = 0; ss < 4; ss++)
                #pragma unroll
                for (int v = 0; v < 4; v++) acc3[ss][v] = 0.0f;
            #pragma unroll
            for (int tap = 0; tap < 5; tap++) {
                #pragma unroll
                for (int cc = 0; cc < 4; cc++) {
                    uint32_t f0, f1;
                    ldsm_x2t(f0, f1, smb + W3_OFF + (tap * 64 + cc * 16 + arow) * 16);
                    #pragma unroll
                    for (int ss = 0; ss < 4; ss++) {
                        uint32_t a0, a1, a2, a3;
                        ldsm_x4(a0, a1, a2, a3,
                                smb + H2_OFF + (r0 + ss * 16 + tap + arow) * RSB
                                    + (cc * 16 + acolB) * 2);
                        mma16816(acc3[ss][0], acc3[ss][1], acc3[ss][2], acc3[ss][3],
                                 a0, a1, a2, a3, f0, f1);
                    }
                }
            }
            int colb = (lane & 3) * 2;
            #pragma unroll
            for (int ss = 0; ss < 4; ss++) {
                int rA = r0 + ss * 16 + (lane >> 2);
                *(float2*)&sD3[rA * 8 + colb]       = make_float2(acc3[ss][0], acc3[ss][1]);
                *(float2*)&sD3[(rA + 8) * 8 + colb] = make_float2(acc3[ss][2], acc3[ss][3]);
            }
        }
        __syncthreads();

        // ---- grad ----
        for (int ic = tid; ic < G_N; ic += NTHREADS) {
            float c0 = sD3[ic * 8 + 0] + sb3[0];
            float c1 = sD3[ic * 8 + 1] + sb3[1];
            float c2 = sD3[ic * 8 + 2] + sb3[2];
            float c3 = sD3[ic * 8 + 3] + sb3[3];
            float p0 = sP[ic + 4], p1 = sP[ic + 5], p2 = sP[ic + 6],
                  p3 = sP[ic + 7], p4 = sP[ic + 8];
            float dotp = AP0 * p0 + AP1 * p1 + AP3 * p3 + AP4 * p4;
            float S4   = p1 + p2 + p3 + p4;
            float base = NB_P0 * p0 + NB_S4 * S4;
            float corr = c0 * (base + p1) + c1 * (base + p2)
                       + c2 * (base + p3) + c3 * (base + p4);
            sg[ic] = (dotp + corr) * 64.0f;
        }
        __syncthreads();

        // ---- TVD limiter ----
        for (int p = tid; p < PHI_N; p += NTHREADS) {
            float gcur = sg[p + 1];
            float gpre = sg[p];
            float aa = (gcur < 0.0f) ? -1.0f : 1.0f;
            float ri = gpre / (fmaxf(fabsf(gcur), 1e-15f) * aa);
            sphi[p] = (ri * ri + ri) / (ri * ri + 1.0f);
        }
        __syncthreads();

        // ---- Godunov flux + update + store ----
        for (int j = tid; j < TILE; j += NTHREADS) {
            float fl[2];
            #pragma unroll
            for (int u = 0; u < 2; u++) {
                int f = j - 1 + u;
                float uL = fmaf(DXH * sphi[f + 1], sg[f + 2], sP[f + 8]);
                float uR = fmaf(-DXH * sphi[f + 2], sg[f + 3], sP[f + 9]);
                fl[u] = 0.25f * (uL * uL + uR * uR)
                      - 0.25f * fabsf(uL + uR) * (uR - uL);
            }
            int gidx = (s + j) & (LLEN - 1);
            Out[(size_t)b * LLEN + gidx] = sP[j + 8] - CFL * (fl[1] - fl[0]);
        }
        __syncthreads();   // flux reads of sP done before halo overwrite

        // ---- commit prefetched halo ----
        if (hn) {
            #pragma unroll
            for (int k = 0; k < 3; k++) {
                int idx = tid + k * NTHREADS;
                if (idx < Y_N) {
                    sP[idx] = pn[k];
                    sy[idx] = (pn[k] - mn2) * inv2 - 1.0f;
                }
            }
        }
        __syncthreads();
    }
}

// ---------------------------------------------------------------------------
// Launch (no statics, no device queries — graph-capture safe)
// ---------------------------------------------------------------------------
extern "C" void kernel_launch(void* const* d_in, const int* in_sizes, int n_in,
                              void* d_out, int out_size) {
    const float* Prim = (const float*)d_in[0];
    const float* W1   = (const float*)d_in[1];
    const float* b1   = (const float*)d_in[2];
    const float* W2   = (const float*)d_in[3];
    const float* b2   = (const float*)d_in[4];
    const float* W3   = (const float*)d_in[5];
    const float* b3   = (const float*)d_in[6];
    float* Out = (float*)d_out;

    int B  = in_sizes[0] / LLEN;
    int NT = B * NTILES;

    cudaFuncSetAttribute(fused_kernel,
                         cudaFuncAttributeMaxDynamicSharedMemorySize, SMEM_DYN);

    int grid = GRID_SM;
    if (grid > NT) grid = NT;

    prep_kernel<<<B + 1, 1024>>>(Prim, W2, W3, B);
    fused_kernel<<<grid, NTHREADS, SMEM_DYN>>>(
        Prim, W1, b1, b2, b3, Out, NT, grid);
}